// round 1
// baseline (speedup 1.0000x reference)
#include <cuda_runtime.h>
#include <math.h>

// Problem dims
#define Nb 64
#define Tt 512
#define Ii 512
#define Hh 1024
#define Oo 512
#define MROWS (Nb*Tt)      // 32768 logical rows (t*Nb + n)
#define NH (Nb*Hh)         // 65536 elements per RNN step state
#define KSPLIT 16
#define RNN_NCTA 128

typedef unsigned long long ull;

// ---------------- scratch (static device arrays; no allocation) ----------------
__device__ float g_inp_v[(size_t)Tt * NH];      // [T][N][H]
__device__ float g_hs_v [(size_t)Tt * NH];      // [T][N][H]
__device__ float g_tmp  [(size_t)Tt * Nb * Oo]; // out_v [T][N][O]
__device__ float g_out_t[(size_t)Tt * Nb * Oo]; // thalamic [T][N][O]
__device__ float g_inp_m[(size_t)Tt * NH];
__device__ float g_hs_m [(size_t)Tt * NH];
__device__ float g_part [KSPLIT * NH];          // k-split partial sums
__device__ unsigned g_bar_cnt;
__device__ volatile unsigned g_bar_gen;

// ---------------- helpers ----------------
__device__ __forceinline__ ull ffma2(ull a, ull b, ull c) {
    ull d;
    asm("fma.rn.f32x2 %0, %1, %2, %3;" : "=l"(d) : "l"(a), "l"(b), "l"(c));
    return d;
}
__device__ __forceinline__ float2 unpack2(ull v) {
    float2 r;
    asm("mov.b64 {%0, %1}, %2;" : "=f"(r.x), "=f"(r.y) : "l"(v));
    return r;
}
__device__ __forceinline__ float retanh(float x) {
    return x > 0.f ? tanhf(x) : 0.f;
}

__global__ void reset_barrier_kernel() {
    g_bar_cnt = 0u;
    g_bar_gen = 0u;
}

__device__ __forceinline__ void grid_barrier(unsigned target) {
    __syncthreads();
    if (threadIdx.x == 0) {
        __threadfence();
        unsigned old = atomicAdd(&g_bar_cnt, 1u);
        if (old == RNN_NCTA - 1) {
            g_bar_cnt = 0u;
            __threadfence();
            g_bar_gen = target;   // release
        } else {
            while (g_bar_gen < target) { }
        }
        __threadfence();
    }
    __syncthreads();
}

// ---------------- generic tiled GEMM: C = act(A[M,K] * W[Nc,K]^T + bias) --------
// 128x128 tile, BK=8, 256 threads, 8x8 per thread, f32x2 packed FMA.
// AMAP=1: logical row r=(t*64+n) reads physical A row n*512+t (data is [N,T,I]).
// CMAP=1: logical row r=(t*64+n) writes physical C row n*512+t (out is [N,T,O]).
template<int AMAP, int CMAP, int RET>
__global__ void __launch_bounds__(256) gemm128(
    const float* __restrict__ A, const float* __restrict__ W,
    const float* __restrict__ bias, float* __restrict__ C,
    int M, int Nc, int K)
{
    __shared__ float As[8][128];
    __shared__ float Ws[8][256];   // W duplicated: Ws[k][2c]=Ws[k][2c+1]=W[n0+c][k]

    const int tid = threadIdx.x;
    const int m0 = blockIdx.x * 128;
    const int n0 = blockIdx.y * 128;
    const int tx = tid & 15, ty = tid >> 4;
    const int lrow = tid >> 1;
    const int lk = (tid & 1) * 4;

    int arow = m0 + lrow;
    if (AMAP) { int nn = arow & 63; int tt = arow >> 6; arow = nn * Tt + tt; }
    const float* Ap = A + (size_t)arow * K + lk;
    const float* Wp = W + (size_t)(n0 + lrow) * K + lk;

    ull acc[4][8];
#pragma unroll
    for (int i = 0; i < 4; i++)
#pragma unroll
        for (int j = 0; j < 8; j++) acc[i][j] = 0ull;

    float4 av = *(const float4*)(Ap);
    float4 wv = *(const float4*)(Wp);

    for (int k0 = 0; k0 < K; k0 += 8) {
        As[lk + 0][lrow] = av.x;
        As[lk + 1][lrow] = av.y;
        As[lk + 2][lrow] = av.z;
        As[lk + 3][lrow] = av.w;
        Ws[lk + 0][2 * lrow] = wv.x; Ws[lk + 0][2 * lrow + 1] = wv.x;
        Ws[lk + 1][2 * lrow] = wv.y; Ws[lk + 1][2 * lrow + 1] = wv.y;
        Ws[lk + 2][2 * lrow] = wv.z; Ws[lk + 2][2 * lrow + 1] = wv.z;
        Ws[lk + 3][2 * lrow] = wv.w; Ws[lk + 3][2 * lrow + 1] = wv.w;
        __syncthreads();
        if (k0 + 8 < K) {
            av = *(const float4*)(Ap + k0 + 8);
            wv = *(const float4*)(Wp + k0 + 8);
        }
#pragma unroll
        for (int kk = 0; kk < 8; kk++) {
            ulonglong2 a01 = *(const ulonglong2*)&As[kk][ty * 8];
            ulonglong2 a23 = *(const ulonglong2*)&As[kk][ty * 8 + 4];
            const ulonglong2* bp = (const ulonglong2*)&Ws[kk][tx * 16];
            ulonglong2 b0 = bp[0], b1 = bp[1], b2 = bp[2], b3 = bp[3];
            ull avv[4] = { a01.x, a01.y, a23.x, a23.y };
            ull bvv[8] = { b0.x, b0.y, b1.x, b1.y, b2.x, b2.y, b3.x, b3.y };
#pragma unroll
            for (int i = 0; i < 4; i++)
#pragma unroll
                for (int j = 0; j < 8; j++)
                    acc[i][j] = ffma2(avv[i], bvv[j], acc[i][j]);
        }
        __syncthreads();
    }

    // epilogue: acc[i] packs rows (m0+ty*8+2i, +2i+1)
#pragma unroll
    for (int i = 0; i < 4; i++) {
        float o0[8], o1[8];
#pragma unroll
        for (int j = 0; j < 8; j++) {
            float2 u = unpack2(acc[i][j]);
            float bcol = bias[n0 + tx * 8 + j];
            float x0 = u.x + bcol, x1 = u.y + bcol;
            if (RET) { x0 = retanh(x0); x1 = retanh(x1); }
            o0[j] = x0; o1[j] = x1;
        }
        int r0 = m0 + ty * 8 + 2 * i;
        int r1 = r0 + 1;
        int cr0 = r0, cr1 = r1;
        if (CMAP) {
            cr0 = (r0 & 63) * Tt + (r0 >> 6);
            cr1 = (r1 & 63) * Tt + (r1 >> 6);
        }
        float4* p0 = (float4*)(C + (size_t)cr0 * Nc + n0 + tx * 8);
        p0[0] = make_float4(o0[0], o0[1], o0[2], o0[3]);
        p0[1] = make_float4(o0[4], o0[5], o0[6], o0[7]);
        float4* p1 = (float4*)(C + (size_t)cr1 * Nc + n0 + tx * 8);
        p1[0] = make_float4(o1[0], o1[1], o1[2], o1[3]);
        p1[1] = make_float4(o1[4], o1[5], o1[6], o1[7]);
    }
}

// ---------------- persistent RNN: h_t = retanh(inp_t + h_{t-1} Wh^T + bh) -------
// 128 CTAs (all resident). Per step:
//   phase A: CTA (htile = bx&7 [128 h cols], ks = bx>>3 [64 k]) computes partial
//            part[ks][n][h] = sum_k hprev[n][k] * Wh[h][k]   (64n x 128h tile)
//   barrier
//   phase B: all CTAs reduce 16 partials + inp + bh, retanh, write hs[t]
//   barrier
__global__ void __launch_bounds__(256) rnn_persistent(
    const float* __restrict__ h0, const float* __restrict__ Wh,
    const float* __restrict__ bh, const float* __restrict__ inp,
    float* __restrict__ hs)
{
    __shared__ float Hs[8][64];    // [k][n]
    __shared__ float Ws[8][256];   // [k][2h] duplicated

    const int tid = threadIdx.x;
    const int bx = blockIdx.x;
    const int htile = bx & 7;
    const int ks = bx >> 3;
    const int h0c = htile * 128;
    const int kbase = ks * 64;
    const int tx = tid & 15, ty = tid >> 4;

    const int wrow = tid >> 1;          // 0..127 (h within tile)
    const int wk4 = (tid & 1) * 4;
    const int hrow = tid >> 2;          // 0..63 (n)
    const int hk2 = (tid & 3) * 2;

    const int e2 = (bx * 256 + tid) * 2; // reduce-phase element base (2 per thread)
    const int rn = e2 >> 10;
    const int rh = e2 & 1023;

    float* pb = g_part + (size_t)ks * NH;
    unsigned gen = 0;

    for (int t = 0; t < Tt; ++t) {
        const float* hprev = t ? (hs + (size_t)(t - 1) * NH) : h0;

        ull acc[2][8];
#pragma unroll
        for (int i = 0; i < 2; i++)
#pragma unroll
            for (int j = 0; j < 8; j++) acc[i][j] = 0ull;

        float2 hv = *(const float2*)(hprev + (size_t)hrow * Hh + kbase + hk2);
        float4 wv = *(const float4*)(Wh + (size_t)(h0c + wrow) * Hh + kbase + wk4);

        for (int k0 = 0; k0 < 64; k0 += 8) {
            Hs[hk2][hrow] = hv.x;
            Hs[hk2 + 1][hrow] = hv.y;
            Ws[wk4 + 0][2 * wrow] = wv.x; Ws[wk4 + 0][2 * wrow + 1] = wv.x;
            Ws[wk4 + 1][2 * wrow] = wv.y; Ws[wk4 + 1][2 * wrow + 1] = wv.y;
            Ws[wk4 + 2][2 * wrow] = wv.z; Ws[wk4 + 2][2 * wrow + 1] = wv.z;
            Ws[wk4 + 3][2 * wrow] = wv.w; Ws[wk4 + 3][2 * wrow + 1] = wv.w;
            __syncthreads();
            if (k0 + 8 < 64) {
                hv = *(const float2*)(hprev + (size_t)hrow * Hh + kbase + k0 + 8 + hk2);
                wv = *(const float4*)(Wh + (size_t)(h0c + wrow) * Hh + kbase + k0 + 8 + wk4);
            }
#pragma unroll
            for (int kk = 0; kk < 8; kk++) {
                ulonglong2 a01 = *(const ulonglong2*)&Hs[kk][ty * 4];
                const ulonglong2* bp = (const ulonglong2*)&Ws[kk][tx * 16];
                ulonglong2 b0 = bp[0], b1 = bp[1], b2 = bp[2], b3 = bp[3];
                ull bvv[8] = { b0.x, b0.y, b1.x, b1.y, b2.x, b2.y, b3.x, b3.y };
#pragma unroll
                for (int j = 0; j < 8; j++) {
                    acc[0][j] = ffma2(a01.x, bvv[j], acc[0][j]);
                    acc[1][j] = ffma2(a01.y, bvv[j], acc[1][j]);
                }
            }
            __syncthreads();
        }

        // write partials (acc[i2][j]: lo -> n=ty*4+2*i2, hi -> +1)
#pragma unroll
        for (int i2 = 0; i2 < 2; i2++) {
            float lo[8], hi[8];
#pragma unroll
            for (int j = 0; j < 8; j++) {
                float2 u = unpack2(acc[i2][j]);
                lo[j] = u.x; hi[j] = u.y;
            }
            int nlo = ty * 4 + 2 * i2;
            float4* plo = (float4*)(pb + (size_t)nlo * Hh + h0c + tx * 8);
            plo[0] = make_float4(lo[0], lo[1], lo[2], lo[3]);
            plo[1] = make_float4(lo[4], lo[5], lo[6], lo[7]);
            float4* phi = (float4*)(pb + (size_t)(nlo + 1) * Hh + h0c + tx * 8);
            phi[0] = make_float4(hi[0], hi[1], hi[2], hi[3]);
            phi[1] = make_float4(hi[4], hi[5], hi[6], hi[7]);
        }

        grid_barrier(++gen);

        // reduce + activation
        {
            float2 s = *(const float2*)(inp + (size_t)t * NH + e2);
            float2 bb = *(const float2*)(bh + rh);
            s.x += bb.x; s.y += bb.y;
#pragma unroll
            for (int p = 0; p < KSPLIT; p++) {
                float2 pv = *(const float2*)(g_part + (size_t)p * NH + e2);
                s.x += pv.x; s.y += pv.y;
            }
            s.x = retanh(s.x);
            s.y = retanh(s.y);
            *(float2*)(hs + (size_t)t * NH + e2) = s;
        }

        grid_barrier(++gen);
        (void)rn;
    }
}

// ---------------- host ----------------
extern "C" void kernel_launch(void* const* d_in, const int* in_sizes, int n_in,
                              void* d_out, int out_size)
{
    const float* data = (const float*)d_in[0];
    const float* h0v  = (const float*)d_in[1];
    const float* h0m  = (const float*)d_in[2];
    const float* Wi   = (const float*)d_in[3];
    const float* bi   = (const float*)d_in[4];
    const float* Wh   = (const float*)d_in[5];
    const float* bh   = (const float*)d_in[6];
    const float* Wo   = (const float*)d_in[7];
    const float* bo   = (const float*)d_in[8];
    const float* Wt   = (const float*)d_in[9];
    const float* bt   = (const float*)d_in[10];
    const float* Wi2  = (const float*)d_in[11];
    const float* bi2  = (const float*)d_in[12];
    const float* Wh2  = (const float*)d_in[13];
    const float* bh2  = (const float*)d_in[14];
    const float* Wo2  = (const float*)d_in[15];
    const float* bo2  = (const float*)d_in[16];
    float* out = (float*)d_out;

    float *inpv, *hsv, *tmp, *outt, *inpm, *hsm;
    cudaGetSymbolAddress((void**)&inpv, g_inp_v);
    cudaGetSymbolAddress((void**)&hsv,  g_hs_v);
    cudaGetSymbolAddress((void**)&tmp,  g_tmp);
    cudaGetSymbolAddress((void**)&outt, g_out_t);
    cudaGetSymbolAddress((void**)&inpm, g_inp_m);
    cudaGetSymbolAddress((void**)&hsm,  g_hs_m);

    dim3 blk(256);

    // 1) visual input projection: inp_v[t,n,:] = data[n,t,:] @ Wi^T + bi
    gemm128<1, 0, 0><<<dim3(MROWS / 128, Hh / 128), blk>>>(data, Wi, bi, inpv, MROWS, Hh, Ii);

    // 2) visual RNN
    reset_barrier_kernel<<<1, 1>>>();
    rnn_persistent<<<RNN_NCTA, blk>>>(h0v, Wh, bh, inpv, hsv);

    // 3) out_v = hs_v @ Wo^T + bo
    gemm128<0, 0, 0><<<dim3(MROWS / 128, Oo / 128), blk>>>(hsv, Wo, bo, tmp, MROWS, Oo, Hh);

    // 4) out_t = retanh(out_v @ Wt^T + bt)
    gemm128<0, 0, 1><<<dim3(MROWS / 128, Oo / 128), blk>>>(tmp, Wt, bt, outt, MROWS, Oo, Oo);

    // 5) motor input projection: inp_m = out_t @ Wi2^T + bi2
    gemm128<0, 0, 0><<<dim3(MROWS / 128, Hh / 128), blk>>>(outt, Wi2, bi2, inpm, MROWS, Hh, Oo);

    // 6) motor RNN
    reset_barrier_kernel<<<1, 1>>>();
    rnn_persistent<<<RNN_NCTA, blk>>>(h0m, Wh2, bh2, inpm, hsm);

    // 7) out_m[n,t,:] = hs_m[t,n,:] @ Wo2^T + bo2
    gemm128<0, 1, 0><<<dim3(MROWS / 128, Oo / 128), blk>>>(hsm, Wo2, bo2, out, MROWS, Oo, Hh);
}

// round 2
// speedup vs baseline: 2.0613x; 2.0613x over previous
#include <cuda_runtime.h>
#include <math.h>

// Problem dims
#define Nb 64
#define Tt 512
#define Ii 512
#define Hh 1024
#define Oo 512
#define MROWS (Nb*Tt)      // 32768 logical rows (t*Nb + n)
#define NH (Nb*Hh)         // 65536 elements per RNN step state
#define RNN_NCTA 128

typedef unsigned long long ull;

// ---------------- scratch ----------------
__device__ float g_inp_v[(size_t)Tt * NH];
__device__ float g_hs_v [(size_t)Tt * NH];
__device__ float g_tmp  [(size_t)Tt * Nb * Oo];
__device__ float g_out_t[(size_t)Tt * Nb * Oo];
__device__ float g_inp_m[(size_t)Tt * NH];
__device__ float g_hs_m [(size_t)Tt * NH];
__device__ unsigned g_bar_cnt;
__device__ volatile unsigned g_bar_gen;

// ---------------- helpers ----------------
__device__ __forceinline__ ull ffma2(ull a, ull b, ull c) {
    ull d;
    asm("fma.rn.f32x2 %0, %1, %2, %3;" : "=l"(d) : "l"(a), "l"(b), "l"(c));
    return d;
}
__device__ __forceinline__ float2 unpack2(ull v) {
    float2 r;
    asm("mov.b64 {%0, %1}, %2;" : "=f"(r.x), "=f"(r.y) : "l"(v));
    return r;
}
__device__ __forceinline__ ull dup2(float v) {
    ull r;
    asm("mov.b64 %0, {%1, %1};" : "=l"(r) : "f"(v));
    return r;
}
__device__ __forceinline__ float retanh(float x) {
    return x > 0.f ? tanhf(x) : 0.f;
}

__global__ void reset_barrier_kernel() {
    g_bar_cnt = 0u;
    g_bar_gen = 0u;
}

__device__ __forceinline__ void grid_barrier(unsigned target) {
    __syncthreads();
    if (threadIdx.x == 0) {
        __threadfence();
        unsigned old = atomicAdd(&g_bar_cnt, 1u);
        if (old == RNN_NCTA - 1) {
            g_bar_cnt = 0u;
            __threadfence();
            g_bar_gen = target;
        } else {
            while (g_bar_gen < target) { }
        }
        __threadfence();
    }
    __syncthreads();
}

// ---------------- GEMM: C = act(A[M,K] * W[Nc,K]^T + bias) ----------------
// 128x128 tile, BK=8, 256 threads (8 warps: 4 m-warps x 2 n-warps).
// Warp tile 32m x 64n; thread tile 8m x 8n; f32x2 paired along m.
// Conflict-free A frag (lanes at 32B stride -> banks 0/8/16/24), 2-way B frag.
template<int AMAP, int CMAP, int RET>
__global__ void __launch_bounds__(256, 2) gemm128(
    const float* __restrict__ A, const float* __restrict__ W,
    const float* __restrict__ bias, float* __restrict__ C,
    int M, int Nc, int K)
{
    __shared__ float As[8][128];
    __shared__ float Bs[8][128];

    const int tid = threadIdx.x;
    const int m0 = blockIdx.x * 128;
    const int n0 = blockIdx.y * 128;

    const int warp = tid >> 5;
    const int lane = tid & 31;
    const int wm = warp & 3;        // m-warp (x32)
    const int wn = warp >> 2;       // n-warp (x64)
    const int tm = lane & 3;        // x8 m per thread
    const int tn = lane >> 2;       // x8 n per thread

    // staging indices
    const int srow = tid >> 1;
    const int sk = (tid & 1) * 4;

    int arow = m0 + srow;
    if (AMAP) { int nn = arow & 63; int tt = arow >> 6; arow = nn * Tt + tt; }
    const float* Ap = A + (size_t)arow * K + sk;
    const float* Wp = W + (size_t)(n0 + srow) * K + sk;

    ull acc[4][8];
#pragma unroll
    for (int i = 0; i < 4; i++)
#pragma unroll
        for (int j = 0; j < 8; j++) acc[i][j] = 0ull;

    float4 av = *(const float4*)(Ap);
    float4 wv = *(const float4*)(Wp);

    const int aoff = wm * 32 + tm * 8;
    const int boff = wn * 64 + tn * 8;

    for (int k0 = 0; k0 < K; k0 += 8) {
        As[sk + 0][srow] = av.x;
        As[sk + 1][srow] = av.y;
        As[sk + 2][srow] = av.z;
        As[sk + 3][srow] = av.w;
        Bs[sk + 0][srow] = wv.x;
        Bs[sk + 1][srow] = wv.y;
        Bs[sk + 2][srow] = wv.z;
        Bs[sk + 3][srow] = wv.w;
        __syncthreads();
        if (k0 + 8 < K) {
            av = *(const float4*)(Ap + k0 + 8);
            wv = *(const float4*)(Wp + k0 + 8);
        }
#pragma unroll
        for (int kk = 0; kk < 8; kk++) {
            ulonglong2 a01 = *(const ulonglong2*)&As[kk][aoff];
            ulonglong2 a23 = *(const ulonglong2*)&As[kk][aoff + 4];
            float4 b0 = *(const float4*)&Bs[kk][boff];
            float4 b1 = *(const float4*)&Bs[kk][boff + 4];
            ull avv[4] = { a01.x, a01.y, a23.x, a23.y };
            ull bd[8];
            bd[0] = dup2(b0.x); bd[1] = dup2(b0.y);
            bd[2] = dup2(b0.z); bd[3] = dup2(b0.w);
            bd[4] = dup2(b1.x); bd[5] = dup2(b1.y);
            bd[6] = dup2(b1.z); bd[7] = dup2(b1.w);
#pragma unroll
            for (int i = 0; i < 4; i++)
#pragma unroll
                for (int j = 0; j < 8; j++)
                    acc[i][j] = ffma2(avv[i], bd[j], acc[i][j]);
        }
        __syncthreads();
    }

    // bias for this thread's 8 n columns
    float bb[8];
#pragma unroll
    for (int j = 0; j < 8; j++) bb[j] = bias[n0 + boff + j];

#pragma unroll
    for (int i = 0; i < 4; i++) {
        float o0[8], o1[8];
#pragma unroll
        for (int j = 0; j < 8; j++) {
            float2 u = unpack2(acc[i][j]);
            float x0 = u.x + bb[j], x1 = u.y + bb[j];
            if (RET) { x0 = retanh(x0); x1 = retanh(x1); }
            o0[j] = x0; o1[j] = x1;
        }
        int r0 = m0 + aoff + 2 * i;
        int r1 = r0 + 1;
        int cr0 = r0, cr1 = r1;
        if (CMAP) {
            cr0 = (r0 & 63) * Tt + (r0 >> 6);
            cr1 = (r1 & 63) * Tt + (r1 >> 6);
        }
        float4* p0 = (float4*)(C + (size_t)cr0 * Nc + n0 + boff);
        p0[0] = make_float4(o0[0], o0[1], o0[2], o0[3]);
        p0[1] = make_float4(o0[4], o0[5], o0[6], o0[7]);
        float4* p1 = (float4*)(C + (size_t)cr1 * Nc + n0 + boff);
        p1[0] = make_float4(o1[0], o1[1], o1[2], o1[3]);
        p1[1] = make_float4(o1[4], o1[5], o1[6], o1[7]);
    }
}

// ---------------- persistent RNN (single-phase) ----------------
// 128 CTAs x 256 thr. CTA tile = 16n x 32h, full K=1024 per step.
// W tile (32 rows x 1024) staged in smem ONCE (rotated layout, conflict-free),
// hprev streamed per 128-k chunk. One grid barrier per step.
// smem floats: W 32*1056, H 16*132
#define W_STRIDE 1056          // 1024 + 8 pad floats (4224B rows)
#define H_STRIDE 132
#define RNN_SMEM_FLOATS (32 * W_STRIDE + 16 * H_STRIDE)
#define RNN_SMEM_BYTES (RNN_SMEM_FLOATS * 4)

__global__ void __launch_bounds__(256, 1) rnn_persistent(
    const float* __restrict__ h0, const float* __restrict__ Wh,
    const float* __restrict__ bh, const float* __restrict__ inp,
    float* __restrict__ hs)
{
    extern __shared__ float sm[];
    float* smW = sm;                       // [32][W_STRIDE] rotated
    float* smH = sm + 32 * W_STRIDE;       // [16][H_STRIDE]

    const int tid = threadIdx.x;
    const int bx = blockIdx.x;
    const int gn = bx >> 5;        // n-group (4)  -> 16 n rows
    const int gh = bx & 31;        // h-group (32) -> 32 h cols

    const int lane = tid & 31;
    const int wid = tid >> 5;
    const int lh = lane & 7;
    const int ln = lane >> 3;      // 0..3
    const int jgrp = wid >> 2;     // 0..1
    const int n_local = (wid & 3) * 4 + ln;   // 0..15
    // thread's 2 h columns: lh + 8*(2*jgrp + j), j in {0,1}
    const int h_loc0 = lh + 16 * jgrp;
    const int h_loc1 = h_loc0 + 8;

    const int n_global = gn * 16 + n_local;
    const int h_glob0 = gh * 32 + h_loc0;
    const int h_glob1 = gh * 32 + h_loc1;

    // ---- stage W once (rotated: row h at h*W_STRIDE + (h&7)*4 floats) ----
    for (int idx4 = tid; idx4 < 8192; idx4 += 256) {
        int idx = idx4 * 4;
        int h = idx >> 10;
        int k = idx & 1023;
        float4 v = *(const float4*)(Wh + (size_t)(gh * 32 + h) * Hh + k);
        *(float4*)(smW + h * W_STRIDE + (h & 7) * 4 + k) = v;
    }
    __syncthreads();

    // per-thread W base pointers (float index), advance by 4 floats per k4
    const float* wb0 = smW + h_loc0 * W_STRIDE + (h_loc0 & 7) * 4;
    const float* wb1 = smW + h_loc1 * W_STRIDE + (h_loc1 & 7) * 4;
    const float* hb = smH + n_local * H_STRIDE;

    float bh0 = bh[h_glob0];
    float bh1 = bh[h_glob1];

    unsigned gen = 0;

    for (int t = 0; t < Tt; ++t) {
        const float* hprev = t ? (hs + (size_t)(t - 1) * NH) : h0;

        ull acc0 = 0ull, acc1 = 0ull;

        // prefetch chunk 0 (each thread: 2 float4 of the 16x128 chunk)
        float4 pf0, pf1;
        {
            int i40 = tid, i41 = tid + 256;
            int r0 = i40 >> 5, c0 = (i40 & 31) * 4;
            int r1 = i41 >> 5, c1 = (i41 & 31) * 4;
            pf0 = *(const float4*)(hprev + (size_t)(gn * 16 + r0) * Hh + c0);
            pf1 = *(const float4*)(hprev + (size_t)(gn * 16 + r1) * Hh + c1);
        }

        for (int c = 0; c < 8; c++) {
            __syncthreads();
            {
                int i40 = tid, i41 = tid + 256;
                int r0 = i40 >> 5, c0 = (i40 & 31) * 4;
                int r1 = i41 >> 5, c1 = (i41 & 31) * 4;
                *(float4*)(smH + r0 * H_STRIDE + c0) = pf0;
                *(float4*)(smH + r1 * H_STRIDE + c1) = pf1;
            }
            __syncthreads();
            if (c < 7) {
                int i40 = tid, i41 = tid + 256;
                int r0 = i40 >> 5, c0 = (i40 & 31) * 4;
                int r1 = i41 >> 5, c1 = (i41 & 31) * 4;
                pf0 = *(const float4*)(hprev + (size_t)(gn * 16 + r0) * Hh + (c + 1) * 128 + c0);
                pf1 = *(const float4*)(hprev + (size_t)(gn * 16 + r1) * Hh + (c + 1) * 128 + c1);
            }
            const float* w0p = wb0 + c * 128;
            const float* w1p = wb1 + c * 128;
#pragma unroll
            for (int i = 0; i < 32; i++) {
                ulonglong2 hv = *(const ulonglong2*)(hb + i * 4);
                ulonglong2 w0 = *(const ulonglong2*)(w0p + i * 4);
                ulonglong2 w1 = *(const ulonglong2*)(w1p + i * 4);
                acc0 = ffma2(hv.x, w0.x, acc0);
                acc0 = ffma2(hv.y, w0.y, acc0);
                acc1 = ffma2(hv.x, w1.x, acc1);
                acc1 = ffma2(hv.y, w1.y, acc1);
            }
        }

        // epilogue: horizontal add + inp + bias + retanh
        {
            const float* ip = inp + (size_t)t * NH + (size_t)n_global * Hh;
            float* op = hs + (size_t)t * NH + (size_t)n_global * Hh;
            float2 u0 = unpack2(acc0);
            float2 u1 = unpack2(acc1);
            float s0 = u0.x + u0.y + ip[h_glob0 - gh * 32 + gh * 32] + bh0;
            float s1 = u1.x + u1.y + ip[h_glob1 - gh * 32 + gh * 32] + bh1;
            // (simplify: ip indexed by global h)
            s0 = retanh(s0);
            s1 = retanh(s1);
            op[h_glob0] = s0;
            op[h_glob1] = s1;
        }

        grid_barrier(++gen);
    }
}

// ---------------- host ----------------
extern "C" void kernel_launch(void* const* d_in, const int* in_sizes, int n_in,
                              void* d_out, int out_size)
{
    const float* data = (const float*)d_in[0];
    const float* h0v  = (const float*)d_in[1];
    const float* h0m  = (const float*)d_in[2];
    const float* Wi   = (const float*)d_in[3];
    const float* bi   = (const float*)d_in[4];
    const float* Wh   = (const float*)d_in[5];
    const float* bh   = (const float*)d_in[6];
    const float* Wo   = (const float*)d_in[7];
    const float* bo   = (const float*)d_in[8];
    const float* Wt   = (const float*)d_in[9];
    const float* bt   = (const float*)d_in[10];
    const float* Wi2  = (const float*)d_in[11];
    const float* bi2  = (const float*)d_in[12];
    const float* Wh2  = (const float*)d_in[13];
    const float* bh2  = (const float*)d_in[14];
    const float* Wo2  = (const float*)d_in[15];
    const float* bo2  = (const float*)d_in[16];
    float* out = (float*)d_out;

    float *inpv, *hsv, *tmp, *outt, *inpm, *hsm;
    cudaGetSymbolAddress((void**)&inpv, g_inp_v);
    cudaGetSymbolAddress((void**)&hsv,  g_hs_v);
    cudaGetSymbolAddress((void**)&tmp,  g_tmp);
    cudaGetSymbolAddress((void**)&outt, g_out_t);
    cudaGetSymbolAddress((void**)&inpm, g_inp_m);
    cudaGetSymbolAddress((void**)&hsm,  g_hs_m);

    cudaFuncSetAttribute(rnn_persistent,
                         cudaFuncAttributeMaxDynamicSharedMemorySize, RNN_SMEM_BYTES);

    dim3 blk(256);

    // 1) inp_v[t,n,:] = data[n,t,:] @ Wi^T + bi
    gemm128<1, 0, 0><<<dim3(MROWS / 128, Hh / 128), blk>>>(data, Wi, bi, inpv, MROWS, Hh, Ii);

    // 2) visual RNN
    reset_barrier_kernel<<<1, 1>>>();
    rnn_persistent<<<RNN_NCTA, blk, RNN_SMEM_BYTES>>>(h0v, Wh, bh, inpv, hsv);

    // 3) out_v = hs_v @ Wo^T + bo
    gemm128<0, 0, 0><<<dim3(MROWS / 128, Oo / 128), blk>>>(hsv, Wo, bo, tmp, MROWS, Oo, Hh);

    // 4) out_t = retanh(out_v @ Wt^T + bt)
    gemm128<0, 0, 1><<<dim3(MROWS / 128, Oo / 128), blk>>>(tmp, Wt, bt, outt, MROWS, Oo, Oo);

    // 5) inp_m = out_t @ Wi2^T + bi2
    gemm128<0, 0, 0><<<dim3(MROWS / 128, Hh / 128), blk>>>(outt, Wi2, bi2, inpm, MROWS, Hh, Oo);

    // 6) motor RNN
    reset_barrier_kernel<<<1, 1>>>();
    rnn_persistent<<<RNN_NCTA, blk, RNN_SMEM_BYTES>>>(h0m, Wh2, bh2, inpm, hsm);

    // 7) out_m[n,t,:] = hs_m[t,n,:] @ Wo2^T + bo2
    gemm128<0, 1, 0><<<dim3(MROWS / 128, Oo / 128), blk>>>(hsm, Wo2, bo2, out, MROWS, Oo, Hh);
}

// round 3
// speedup vs baseline: 2.6851x; 1.3026x over previous
#include <cuda_runtime.h>
#include <math.h>

// Problem dims
#define Nb 64
#define Tt 512
#define Ii 512
#define Hh 1024
#define Oo 512
#define MROWS (Nb*Tt)
#define NH (Nb*Hh)
#define RNN_NCTA 128

typedef unsigned long long ull;

// ---------------- scratch ----------------
__device__ float g_inp_v[(size_t)Tt * NH];
__device__ float g_hs_v [(size_t)Tt * NH];
__device__ float g_tmp  [(size_t)Tt * Nb * Oo];
__device__ float g_out_t[(size_t)Tt * Nb * Oo];
__device__ float g_inp_m[(size_t)Tt * NH];
__device__ float g_hs_m [(size_t)Tt * NH];
__device__ unsigned g_bar_cnt;
__device__ volatile unsigned g_bar_gen;

// ---------------- helpers ----------------
__device__ __forceinline__ ull ffma2(ull a, ull b, ull c) {
    ull d;
    asm("fma.rn.f32x2 %0, %1, %2, %3;" : "=l"(d) : "l"(a), "l"(b), "l"(c));
    return d;
}
__device__ __forceinline__ float2 unpack2(ull v) {
    float2 r;
    asm("mov.b64 {%0, %1}, %2;" : "=f"(r.x), "=f"(r.y) : "l"(v));
    return r;
}
__device__ __forceinline__ ull dup2(float v) {
    ull r;
    asm("mov.b64 %0, {%1, %1};" : "=l"(r) : "f"(v));
    return r;
}
__device__ __forceinline__ float retanh(float x) {
    return x > 0.f ? tanhf(x) : 0.f;
}
__device__ __forceinline__ unsigned smem_u32(const void* p) {
    return (unsigned)__cvta_generic_to_shared(p);
}
#define CP_ASYNC16(dst, src) \
    asm volatile("cp.async.cg.shared.global [%0], [%1], 16;" :: "r"(dst), "l"(src))
#define CP_COMMIT() asm volatile("cp.async.commit_group;" ::: "memory")
#define CP_WAIT0()  asm volatile("cp.async.wait_group 0;" ::: "memory")

__global__ void reset_barrier_kernel() {
    g_bar_cnt = 0u;
    g_bar_gen = 0u;
}

__device__ __forceinline__ void grid_barrier(unsigned target) {
    __syncthreads();
    if (threadIdx.x == 0) {
        __threadfence();
        unsigned old = atomicAdd(&g_bar_cnt, 1u);
        if (old == RNN_NCTA - 1) {
            g_bar_cnt = 0u;
            __threadfence();
            g_bar_gen = target;
        } else {
            while (g_bar_gen < target) { }
        }
        __threadfence();
    }
    __syncthreads();
}

// ---------------- GEMM: C = act(A[M,K] * W[Nc,K]^T + bias) ----------------
// (unchanged from R2: 80% of f32x2 peak)
template<int AMAP, int CMAP, int RET>
__global__ void __launch_bounds__(256, 2) gemm128(
    const float* __restrict__ A, const float* __restrict__ W,
    const float* __restrict__ bias, float* __restrict__ C,
    int M, int Nc, int K)
{
    __shared__ float As[8][128];
    __shared__ float Bs[8][128];

    const int tid = threadIdx.x;
    const int m0 = blockIdx.x * 128;
    const int n0 = blockIdx.y * 128;

    const int warp = tid >> 5;
    const int lane = tid & 31;
    const int wm = warp & 3;
    const int wn = warp >> 2;
    const int tm = lane & 3;
    const int tn = lane >> 2;

    const int srow = tid >> 1;
    const int sk = (tid & 1) * 4;

    int arow = m0 + srow;
    if (AMAP) { int nn = arow & 63; int tt = arow >> 6; arow = nn * Tt + tt; }
    const float* Ap = A + (size_t)arow * K + sk;
    const float* Wp = W + (size_t)(n0 + srow) * K + sk;

    ull acc[4][8];
#pragma unroll
    for (int i = 0; i < 4; i++)
#pragma unroll
        for (int j = 0; j < 8; j++) acc[i][j] = 0ull;

    float4 av = *(const float4*)(Ap);
    float4 wv = *(const float4*)(Wp);

    const int aoff = wm * 32 + tm * 8;
    const int boff = wn * 64 + tn * 8;

    for (int k0 = 0; k0 < K; k0 += 8) {
        As[sk + 0][srow] = av.x;
        As[sk + 1][srow] = av.y;
        As[sk + 2][srow] = av.z;
        As[sk + 3][srow] = av.w;
        Bs[sk + 0][srow] = wv.x;
        Bs[sk + 1][srow] = wv.y;
        Bs[sk + 2][srow] = wv.z;
        Bs[sk + 3][srow] = wv.w;
        __syncthreads();
        if (k0 + 8 < K) {
            av = *(const float4*)(Ap + k0 + 8);
            wv = *(const float4*)(Wp + k0 + 8);
        }
#pragma unroll
        for (int kk = 0; kk < 8; kk++) {
            ulonglong2 a01 = *(const ulonglong2*)&As[kk][aoff];
            ulonglong2 a23 = *(const ulonglong2*)&As[kk][aoff + 4];
            float4 b0 = *(const float4*)&Bs[kk][boff];
            float4 b1 = *(const float4*)&Bs[kk][boff + 4];
            ull avv[4] = { a01.x, a01.y, a23.x, a23.y };
            ull bd[8];
            bd[0] = dup2(b0.x); bd[1] = dup2(b0.y);
            bd[2] = dup2(b0.z); bd[3] = dup2(b0.w);
            bd[4] = dup2(b1.x); bd[5] = dup2(b1.y);
            bd[6] = dup2(b1.z); bd[7] = dup2(b1.w);
#pragma unroll
            for (int i = 0; i < 4; i++)
#pragma unroll
                for (int j = 0; j < 8; j++)
                    acc[i][j] = ffma2(avv[i], bd[j], acc[i][j]);
        }
        __syncthreads();
    }

    float bb[8];
#pragma unroll
    for (int j = 0; j < 8; j++) bb[j] = bias[n0 + boff + j];

#pragma unroll
    for (int i = 0; i < 4; i++) {
        float o0[8], o1[8];
#pragma unroll
        for (int j = 0; j < 8; j++) {
            float2 u = unpack2(acc[i][j]);
            float x0 = u.x + bb[j], x1 = u.y + bb[j];
            if (RET) { x0 = retanh(x0); x1 = retanh(x1); }
            o0[j] = x0; o1[j] = x1;
        }
        int r0 = m0 + aoff + 2 * i;
        int r1 = r0 + 1;
        int cr0 = r0, cr1 = r1;
        if (CMAP) {
            cr0 = (r0 & 63) * Tt + (r0 >> 6);
            cr1 = (r1 & 63) * Tt + (r1 >> 6);
        }
        float4* p0 = (float4*)(C + (size_t)cr0 * Nc + n0 + boff);
        p0[0] = make_float4(o0[0], o0[1], o0[2], o0[3]);
        p0[1] = make_float4(o0[4], o0[5], o0[6], o0[7]);
        float4* p1 = (float4*)(C + (size_t)cr1 * Nc + n0 + boff);
        p1[0] = make_float4(o1[0], o1[1], o1[2], o1[3]);
        p1[1] = make_float4(o1[4], o1[5], o1[6], o1[7]);
    }
}

// ---------------- persistent RNN: register-resident W ----------------
// 128 CTAs x 256 thr, CTA owns 8 h columns, full K=1024 per step.
// Thread (h_loc=tid&7, kc4=tid>>3) holds W[h][c*128+kc4*4 .. +3] for c=0..7
// in 32 registers (as 8 ulonglong2). h state streamed global->smem via
// cp.async, double-buffered 128-k chunks. 64 f32x2 accumulators per thread.
// k-reduce: shfl bfly(8,16) intra-warp, then 8-way cross-warp via smem.
#define SMH_STRIDE 132
#define SMH_BUF_FLOATS (64 * SMH_STRIDE)
#define RED_FLOATS (8 * 64 * 8)
#define RNN_SMEM_FLOATS (2 * SMH_BUF_FLOATS + RED_FLOATS)
#define RNN_SMEM_BYTES (RNN_SMEM_FLOATS * 4)

__device__ __forceinline__ void stage_chunk(const float* __restrict__ hprev,
                                            int c, float* __restrict__ dstbuf,
                                            int tid)
{
#pragma unroll
    for (int j = 0; j < 8; j++) {
        int idx = j * 256 + tid;
        int n = idx >> 5;
        int f4 = (idx & 31) * 4;
        CP_ASYNC16(smem_u32(dstbuf + n * SMH_STRIDE + f4),
                   hprev + (size_t)n * Hh + c * 128 + f4);
    }
}

__device__ __forceinline__ void compute_chunk(const float* __restrict__ buf,
                                              int kc4, ull wx, ull wy, ull* acc)
{
    const float* hb = buf + kc4 * 4;
#pragma unroll
    for (int n = 0; n < 64; n += 4) {
        ulonglong2 v0 = *(const ulonglong2*)(hb + (n + 0) * SMH_STRIDE);
        ulonglong2 v1 = *(const ulonglong2*)(hb + (n + 1) * SMH_STRIDE);
        ulonglong2 v2 = *(const ulonglong2*)(hb + (n + 2) * SMH_STRIDE);
        ulonglong2 v3 = *(const ulonglong2*)(hb + (n + 3) * SMH_STRIDE);
        acc[n + 0] = ffma2(v0.x, wx, acc[n + 0]);
        acc[n + 1] = ffma2(v1.x, wx, acc[n + 1]);
        acc[n + 2] = ffma2(v2.x, wx, acc[n + 2]);
        acc[n + 3] = ffma2(v3.x, wx, acc[n + 3]);
        acc[n + 0] = ffma2(v0.y, wy, acc[n + 0]);
        acc[n + 1] = ffma2(v1.y, wy, acc[n + 1]);
        acc[n + 2] = ffma2(v2.y, wy, acc[n + 2]);
        acc[n + 3] = ffma2(v3.y, wy, acc[n + 3]);
    }
}

__global__ void __launch_bounds__(256, 1) rnn_persistent(
    const float* __restrict__ h0, const float* __restrict__ Wh,
    const float* __restrict__ bh, const float* __restrict__ inp,
    float* __restrict__ hs)
{
    extern __shared__ float sm[];
    float* smH0 = sm;
    float* smH1 = sm + SMH_BUF_FLOATS;
    float* red  = sm + 2 * SMH_BUF_FLOATS;   // [warp][n][h_loc] = 8*64*8

    const int tid = threadIdx.x;
    const int gh = blockIdx.x;          // h-group: 8 columns
    const int lane = tid & 31;
    const int wid = tid >> 5;
    const int h_loc = tid & 7;
    const int kc4 = tid >> 3;           // 0..31
    const int hg = gh * 8 + h_loc;      // global h column this thread computes

    // ---- W into registers (permanent) ----
    ulonglong2 Wr[8];
#pragma unroll
    for (int c = 0; c < 8; c++)
        Wr[c] = *(const ulonglong2*)(Wh + (size_t)hg * Hh + c * 128 + kc4 * 4);

    // ---- final-phase mapping + bias preload ----
    const int fn = tid >> 2;            // n row for final reduce
    const int fh = (tid & 3) * 2;       // h pair within group
    float2 bb = *(const float2*)(bh + gh * 8 + fh);

    unsigned gen = 0;

    for (int t = 0; t < Tt; ++t) {
        const float* hprev = t ? (hs + (size_t)(t - 1) * NH) : h0;

        ull acc[64];
#pragma unroll
        for (int n = 0; n < 64; n++) acc[n] = 0ull;

        stage_chunk(hprev, 0, smH0, tid);
        CP_COMMIT();
        CP_WAIT0();
        __syncthreads();

#pragma unroll
        for (int c = 0; c < 8; c++) {
            float* cur = (c & 1) ? smH1 : smH0;
            float* nxt = (c & 1) ? smH0 : smH1;
            if (c < 7) {
                stage_chunk(hprev, c + 1, nxt, tid);
                CP_COMMIT();
            }
            compute_chunk(cur, kc4, Wr[c].x, Wr[c].y, acc);
            if (c < 7) {
                CP_WAIT0();
                __syncthreads();
            }
        }

        // ---- k-reduction ----
        float s[64];
#pragma unroll
        for (int n = 0; n < 64; n++) {
            float2 u = unpack2(acc[n]);
            s[n] = u.x + u.y;
        }
#pragma unroll
        for (int n = 0; n < 64; n++)
            s[n] += __shfl_xor_sync(0xffffffffu, s[n], 8);
#pragma unroll
        for (int n = 0; n < 64; n++)
            s[n] += __shfl_xor_sync(0xffffffffu, s[n], 16);

        if (lane < 8) {
#pragma unroll
            for (int n = 0; n < 64; n++)
                red[wid * 512 + n * 8 + lane] = s[n];
        }
        __syncthreads();

        // ---- final 8-way reduce + inp + bias + retanh + store ----
        {
            float2 r = make_float2(0.f, 0.f);
#pragma unroll
            for (int w2 = 0; w2 < 8; w2++) {
                float2 pv = *(const float2*)(red + w2 * 512 + fn * 8 + fh);
                r.x += pv.x; r.y += pv.y;
            }
            float2 ip = *(const float2*)(inp + (size_t)t * NH + (size_t)fn * Hh + gh * 8 + fh);
            r.x = retanh(r.x + ip.x + bb.x);
            r.y = retanh(r.y + ip.y + bb.y);
            *(float2*)(hs + (size_t)t * NH + (size_t)fn * Hh + gh * 8 + fh) = r;
        }

        grid_barrier(++gen);
    }
}

// ---------------- host ----------------
extern "C" void kernel_launch(void* const* d_in, const int* in_sizes, int n_in,
                              void* d_out, int out_size)
{
    const float* data = (const float*)d_in[0];
    const float* h0v  = (const float*)d_in[1];
    const float* h0m  = (const float*)d_in[2];
    const float* Wi   = (const float*)d_in[3];
    const float* bi   = (const float*)d_in[4];
    const float* Wh   = (const float*)d_in[5];
    const float* bh   = (const float*)d_in[6];
    const float* Wo   = (const float*)d_in[7];
    const float* bo   = (const float*)d_in[8];
    const float* Wt   = (const float*)d_in[9];
    const float* bt   = (const float*)d_in[10];
    const float* Wi2  = (const float*)d_in[11];
    const float* bi2  = (const float*)d_in[12];
    const float* Wh2  = (const float*)d_in[13];
    const float* bh2  = (const float*)d_in[14];
    const float* Wo2  = (const float*)d_in[15];
    const float* bo2  = (const float*)d_in[16];
    float* out = (float*)d_out;

    float *inpv, *hsv, *tmp, *outt, *inpm, *hsm;
    cudaGetSymbolAddress((void**)&inpv, g_inp_v);
    cudaGetSymbolAddress((void**)&hsv,  g_hs_v);
    cudaGetSymbolAddress((void**)&tmp,  g_tmp);
    cudaGetSymbolAddress((void**)&outt, g_out_t);
    cudaGetSymbolAddress((void**)&inpm, g_inp_m);
    cudaGetSymbolAddress((void**)&hsm,  g_hs_m);

    cudaFuncSetAttribute(rnn_persistent,
                         cudaFuncAttributeMaxDynamicSharedMemorySize, RNN_SMEM_BYTES);

    dim3 blk(256);

    // 1) inp_v[t,n,:] = data[n,t,:] @ Wi^T + bi
    gemm128<1, 0, 0><<<dim3(MROWS / 128, Hh / 128), blk>>>(data, Wi, bi, inpv, MROWS, Hh, Ii);

    // 2) visual RNN
    reset_barrier_kernel<<<1, 1>>>();
    rnn_persistent<<<RNN_NCTA, blk, RNN_SMEM_BYTES>>>(h0v, Wh, bh, inpv, hsv);

    // 3) out_v = hs_v @ Wo^T + bo
    gemm128<0, 0, 0><<<dim3(MROWS / 128, Oo / 128), blk>>>(hsv, Wo, bo, tmp, MROWS, Oo, Hh);

    // 4) out_t = retanh(out_v @ Wt^T + bt)
    gemm128<0, 0, 1><<<dim3(MROWS / 128, Oo / 128), blk>>>(tmp, Wt, bt, outt, MROWS, Oo, Oo);

    // 5) inp_m = out_t @ Wi2^T + bi2
    gemm128<0, 0, 0><<<dim3(MROWS / 128, Hh / 128), blk>>>(outt, Wi2, bi2, inpm, MROWS, Hh, Oo);

    // 6) motor RNN
    reset_barrier_kernel<<<1, 1>>>();
    rnn_persistent<<<RNN_NCTA, blk, RNN_SMEM_BYTES>>>(h0m, Wh2, bh2, inpm, hsm);

    // 7) out_m[n,t,:] = hs_m[t,n,:] @ Wo2^T + bo2
    gemm128<0, 1, 0><<<dim3(MROWS / 128, Oo / 128), blk>>>(hsm, Wo2, bo2, out, MROWS, Oo, Hh);
}